// round 12
// baseline (speedup 1.0000x reference)
#include <cuda_runtime.h>
#include <math.h>

#define SQ 2048   // sequence length
#define BB 64     // batch
#define DI 512    // input dim
#define HD 512    // hidden dim
#define G4 2048   // 4*HD

#define NBLK 128          // persistent blocks, 1/SM, co-resident
#define TPB 256           // threads per persistent block (8 warps -> 2/SMSP)
#define WPAD 516          // padded W row (floats)

// ---- device scratch (allocation-free per the rules) ----
__device__ float g_xproj[2048ULL * 64ULL * 2048ULL];  // 1 GiB: x @ W_ih^T
__device__ unsigned long long g_bar;                  // grid barrier ticket counter

// ---- packed f32x2 helpers ----
__device__ __forceinline__ void fma2(unsigned long long& d,
                                     unsigned long long a, unsigned long long b) {
    asm("fma.rn.f32x2 %0, %1, %2, %0;" : "+l"(d) : "l"(a), "l"(b));
}
__device__ __forceinline__ float red2(unsigned long long v) {
    float lo, hi;
    asm("mov.b64 {%0, %1}, %2;" : "=f"(lo), "=f"(hi) : "l"(v));
    return lo + hi;
}

__device__ __forceinline__ float sigf(float x) { return 1.0f / (1.0f + __expf(-x)); }

// Grid-wide barrier: single monotonic u64 ticket counter. Proven best across
// R2/R4/R8; distributed variants (R7 flags, R9 split counters) both regressed
// (spin reads serialize against pending atomics on the polled lines).
// Per-thread fence is required: each thread releases its own h/c stores.
__device__ __forceinline__ void gridbar(unsigned nb) {
    __threadfence();
    __syncthreads();
    if (threadIdx.x == 0) {
        unsigned long long t = atomicAdd(&g_bar, 1ULL) + 1ULL;
        unsigned long long target = ((t + nb - 1ULL) / nb) * (unsigned long long)nb;
        while (*((volatile unsigned long long*)&g_bar) < target) { }
        __threadfence();
    }
    __syncthreads();
}

// ============================================================================
// Kernel 1: x_proj[m][n] = sum_k x[m][k] * W_ih[n][k]     (plain fp32 SGEMM)
// M=131072, N=2048, K=512. 128x128 tile, BK=8, 256 thr, 8x8 microtile.
// ============================================================================
__global__ __launch_bounds__(256, 2)
void xproj_gemm(const float* __restrict__ A, const float* __restrict__ W)
{
    __shared__ float As[8][128];
    __shared__ float Bs[8][128];

    const int bn  = blockIdx.x;
    const int bm  = blockIdx.y;
    const int tid = threadIdx.x;

    const int arow = tid >> 1;
    const int acol = (tid & 1) << 2;
    const float* Ag = A + (size_t)(bm * 128 + arow) * DI + acol;
    const float* Wg = W + (size_t)(bn * 128 + arow) * DI + acol;

    const int tx = tid & 15;
    const int ty = tid >> 4;

    float acc[8][8];
#pragma unroll
    for (int i = 0; i < 8; i++)
#pragma unroll
        for (int j = 0; j < 8; j++) acc[i][j] = 0.0f;

    for (int kt = 0; kt < DI; kt += 8) {
        float4 av = *(const float4*)(Ag + kt);
        float4 wv = *(const float4*)(Wg + kt);
        __syncthreads();
        As[acol + 0][arow] = av.x; As[acol + 1][arow] = av.y;
        As[acol + 2][arow] = av.z; As[acol + 3][arow] = av.w;
        Bs[acol + 0][arow] = wv.x; Bs[acol + 1][arow] = wv.y;
        Bs[acol + 2][arow] = wv.z; Bs[acol + 3][arow] = wv.w;
        __syncthreads();
#pragma unroll
        for (int k = 0; k < 8; k++) {
            float ar[8], br[8];
            *(float4*)(ar)     = *(const float4*)&As[k][ty * 8];
            *(float4*)(ar + 4) = *(const float4*)&As[k][ty * 8 + 4];
            *(float4*)(br)     = *(const float4*)&Bs[k][tx * 8];
            *(float4*)(br + 4) = *(const float4*)&Bs[k][tx * 8 + 4];
#pragma unroll
            for (int i = 0; i < 8; i++)
#pragma unroll
                for (int j = 0; j < 8; j++)
                    acc[i][j] += ar[i] * br[j];
        }
    }

    float* Cp = g_xproj + (size_t)(bm * 128 + ty * 8) * G4 + (size_t)(bn * 128 + tx * 8);
#pragma unroll
    for (int i = 0; i < 8; i++) {
        *(float4*)(Cp + (size_t)i * G4)     = make_float4(acc[i][0], acc[i][1], acc[i][2], acc[i][3]);
        *(float4*)(Cp + (size_t)i * G4 + 4) = make_float4(acc[i][4], acc[i][5], acc[i][6], acc[i][7]);
    }
}

// ============================================================================
// Kernel 2: persistent LSTM recurrence. 128 blocks x 256 threads (2 warps/SMSP).
// NO smem h staging: the dot loop reads h_{t-1} straight from global (fresh
// addresses each step -> no L1 staleness after the barrier; L2 bw is ample).
// Serial chain per step: compute -> store h,c -> barrier -> next compute.
// Block owns hidden j in [bid*4, bid*4+4). Warp w: jl = w>>1, half = w&1.
// Thread = (batch b, j): all 4 gates. Per k4-iter: 1 LDG.128 (h) +
// 4 broadcast LDS.128 (w) + 8 FFMA2. c register-resident for all steps.
// ============================================================================
__global__ __launch_bounds__(TPB, 1)
void lstm_persist(const float* __restrict__ Whh,
                  const float* __restrict__ bih,
                  const float* __restrict__ bhh,
                  float* __restrict__ out)
{
    extern __shared__ float smem[];
    float* w_s = smem;                  // 16 * WPAD  (row r: gate r>>2, hidden r&3)

    const int tid  = threadIdx.x;
    const int bid  = blockIdx.x;
    const int lane = tid & 31;
    const int wid  = tid >> 5;          // 0..7
    const int jl   = wid >> 1;          // local hidden index 0..3
    const int half = wid & 1;           // batch half
    const int b    = half * 32 + lane;  // batch 0..63
    const int j    = bid * 4 + jl;      // global hidden index

    float* out_h = out;
    float* out_c = out + (size_t)SQ * BB * HD;

    // One-time: W_hh rows {g*512 + bid*4 + r} -> w_s[g*4+r][*], padded.
    for (int i = tid; i < 16 * (HD / 4); i += TPB) {
        int row = i >> 7, col = i & 127;
        int grow = (row >> 2) * HD + bid * 4 + (row & 3);
        *(float4*)(w_s + row * WPAD + (col << 2)) =
            *(const float4*)(Whh + (size_t)grow * HD + (col << 2));
    }
    // Biases for this thread's 4 gate columns.
    float bs0 = bih[0 * HD + j] + bhh[0 * HD + j];
    float bs1 = bih[1 * HD + j] + bhh[1 * HD + j];
    float bs2 = bih[2 * HD + j] + bhh[2 * HD + j];
    float bs3 = bih[3 * HD + j] + bhh[3 * HD + j];
    __syncthreads();

    const ulonglong2* w0 = (const ulonglong2*)(w_s + (0 * 4 + jl) * WPAD);
    const ulonglong2* w1 = (const ulonglong2*)(w_s + (1 * 4 + jl) * WPAD);
    const ulonglong2* w2 = (const ulonglong2*)(w_s + (2 * 4 + jl) * WPAD);
    const ulonglong2* w3 = (const ulonglong2*)(w_s + (3 * 4 + jl) * WPAD);

    float c = 0.0f;                     // register-resident cell state

    for (int t = 0; t < SQ; ++t) {
        // Prefetch x_proj (4 values): latency hides under the dot loop.
        const float* xq = g_xproj + ((size_t)t * BB + b) * G4 + j;
        float xp0 = __ldg(xq);
        float xp1 = __ldg(xq + 512);
        float xp2 = __ldg(xq + 1024);
        float xp3 = __ldg(xq + 1536);

        float v0, v1, v2, v3;
        if (t == 0) {
            v0 = v1 = v2 = v3 = 0.0f;   // h_0 = 0
        } else {
            // h_{t-1} straight from global (L2-resident, fresh per step).
            const ulonglong2* __restrict__ hg =
                (const ulonglong2*)(out_h + (size_t)(t - 1) * BB * HD + (size_t)b * HD);
            unsigned long long a0 = 0, a1 = 0, a2 = 0, a3 = 0;  // even-k pair acc
            unsigned long long e0 = 0, e1 = 0, e2 = 0, e3 = 0;  // odd-k pair acc
#pragma unroll 8
            for (int k = 0; k < HD / 4; ++k) {
                ulonglong2 hv = hg[k];
                ulonglong2 wv;
                wv = w0[k]; fma2(a0, hv.x, wv.x); fma2(e0, hv.y, wv.y);
                wv = w1[k]; fma2(a1, hv.x, wv.x); fma2(e1, hv.y, wv.y);
                wv = w2[k]; fma2(a2, hv.x, wv.x); fma2(e2, hv.y, wv.y);
                wv = w3[k]; fma2(a3, hv.x, wv.x); fma2(e3, hv.y, wv.y);
            }
            v0 = red2(a0) + red2(e0);
            v1 = red2(a1) + red2(e1);
            v2 = red2(a2) + red2(e2);
            v3 = red2(a3) + red2(e3);
        }

        // Gates (torch order i, f, g, o) + local state update.
        float ig = sigf(v0 + xp0 + bs0);
        float fg = sigf(v1 + xp1 + bs1);
        float gg = tanhf(v2 + xp2 + bs2);
        float og = sigf(v3 + xp3 + bs3);
        c = fg * c + ig * gg;
        float h = og * tanhf(c);

        size_t o = (size_t)t * BB * HD + (size_t)b * HD + j;
        out_h[o] = h;
        out_c[o] = c;

        if (t + 1 < SQ)
            gridbar(NBLK);   // all h_t globally visible before step t+1 reads
    }
}

// ============================================================================
// Launch: inputs: x, W_ih, W_hh, b_ih, b_hh. Output: [h_out | c_out] fp32.
// ============================================================================
extern "C" void kernel_launch(void* const* d_in, const int* in_sizes, int n_in,
                              void* d_out, int out_size)
{
    (void)in_sizes; (void)n_in; (void)out_size;
    const float* x   = (const float*)d_in[0];
    const float* Wih = (const float*)d_in[1];
    const float* Whh = (const float*)d_in[2];
    const float* bih = (const float*)d_in[3];
    const float* bhh = (const float*)d_in[4];
    float* out = (float*)d_out;

    const int smem_bytes = (16 * WPAD) * (int)sizeof(float);
    cudaFuncSetAttribute(lstm_persist, cudaFuncAttributeMaxDynamicSharedMemorySize, smem_bytes);

    dim3 g1(G4 / 128, (SQ * BB) / 128);   // (16, 1024)
    xproj_gemm<<<g1, 256>>>(x, Wih);
    lstm_persist<<<NBLK, TPB, smem_bytes>>>(Whh, bih, bhh, out);
}

// round 14
// speedup vs baseline: 1.7896x; 1.7896x over previous
#include <cuda_runtime.h>
#include <math.h>

#define SQ 2048   // sequence length
#define BB 64     // batch
#define DI 512    // input dim
#define HD 512    // hidden dim
#define G4 2048   // 4*HD

#define NBLK 128          // persistent blocks, 1/SM, co-resident
#define TPB 256           // threads per persistent block (8 warps -> 2/SMSP)
#define HPAD 516          // padded h row (floats): conflict-free LDS.128
#define WPAD 516

// ---- device scratch (allocation-free per the rules) ----
__device__ float g_xproj[2048ULL * 64ULL * 2048ULL];  // 1 GiB: x @ W_ih^T
// Two-level barrier state. Group counters on separate 128B lines (16 ull slots
// apart); root on its own line. All counters monotonic -> graph-replay safe.
__device__ unsigned long long g_grp[16 * 16];
__device__ unsigned long long g_root;

// ---- packed f32x2 helpers ----
__device__ __forceinline__ void fma2(unsigned long long& d,
                                     unsigned long long a, unsigned long long b) {
    asm("fma.rn.f32x2 %0, %1, %2, %0;" : "+l"(d) : "l"(a), "l"(b));
}
__device__ __forceinline__ float red2(unsigned long long v) {
    float lo, hi;
    asm("mov.b64 {%0, %1}, %2;" : "=f"(lo), "=f"(hi) : "l"(v));
    return lo + hi;
}

__device__ __forceinline__ float sigf(float x) { return 1.0f / (1.0f + __expf(-x)); }

// ---- cp.async helpers (LDGSTS: smem <- L2, no register round trip) ----
__device__ __forceinline__ void cp16(float* dst_smem, const float* src) {
    unsigned saddr = (unsigned)__cvta_generic_to_shared(dst_smem);
    asm volatile("cp.async.cg.shared.global [%0], [%1], 16;" :: "r"(saddr), "l"(src));
}
__device__ __forceinline__ void cp_commit_wait() {
    asm volatile("cp.async.commit_group;");
    asm volatile("cp.async.wait_group 0;" ::: "memory");
}

// Two-level grid barrier. Arrival: 8-deep atomic chain per group counter
// (16 groups in parallel on distinct lines); the 8th arriver of each group
// bumps the root. Detection: EVERY block spins on the root line only — the
// exact single-line spin pattern proven in R2/R8 (R7/R9 regressed by polling
// many atomic-hot lines). Per-thread release fence as before.
__device__ __forceinline__ void gridbar2(int bid) {
    __threadfence();                    // release this thread's h/c stores
    __syncthreads();
    if (threadIdx.x == 0) {
        int grp = bid >> 3;             // 16 groups of 8 blocks
        unsigned long long t = atomicAdd(&g_grp[grp << 4], 1ULL) + 1ULL;
        unsigned long long round = (t + 7ULL) >> 3;        // this group's round
        if ((t & 7ULL) == 0ULL)         // last arriver of the group this round
            atomicAdd(&g_root, 1ULL);
        unsigned long long target = round << 4;            // 16 groups per round
        while (*((volatile unsigned long long*)&g_root) < target) { }
        __threadfence();                // acquire
    }
    __syncthreads();
}

// ============================================================================
// Kernel 1: x_proj[m][n] = sum_k x[m][k] * W_ih[n][k]     (plain fp32 SGEMM)
// M=131072, N=2048, K=512. 128x128 tile, BK=8, 256 thr, 8x8 microtile.
// ============================================================================
__global__ __launch_bounds__(256, 2)
void xproj_gemm(const float* __restrict__ A, const float* __restrict__ W)
{
    __shared__ float As[8][128];
    __shared__ float Bs[8][128];

    const int bn  = blockIdx.x;
    const int bm  = blockIdx.y;
    const int tid = threadIdx.x;

    const int arow = tid >> 1;
    const int acol = (tid & 1) << 2;
    const float* Ag = A + (size_t)(bm * 128 + arow) * DI + acol;
    const float* Wg = W + (size_t)(bn * 128 + arow) * DI + acol;

    const int tx = tid & 15;
    const int ty = tid >> 4;

    float acc[8][8];
#pragma unroll
    for (int i = 0; i < 8; i++)
#pragma unroll
        for (int j = 0; j < 8; j++) acc[i][j] = 0.0f;

    for (int kt = 0; kt < DI; kt += 8) {
        float4 av = *(const float4*)(Ag + kt);
        float4 wv = *(const float4*)(Wg + kt);
        __syncthreads();
        As[acol + 0][arow] = av.x; As[acol + 1][arow] = av.y;
        As[acol + 2][arow] = av.z; As[acol + 3][arow] = av.w;
        Bs[acol + 0][arow] = wv.x; Bs[acol + 1][arow] = wv.y;
        Bs[acol + 2][arow] = wv.z; Bs[acol + 3][arow] = wv.w;
        __syncthreads();
#pragma unroll
        for (int k = 0; k < 8; k++) {
            float ar[8], br[8];
            *(float4*)(ar)     = *(const float4*)&As[k][ty * 8];
            *(float4*)(ar + 4) = *(const float4*)&As[k][ty * 8 + 4];
            *(float4*)(br)     = *(const float4*)&Bs[k][tx * 8];
            *(float4*)(br + 4) = *(const float4*)&Bs[k][tx * 8 + 4];
#pragma unroll
            for (int i = 0; i < 8; i++)
#pragma unroll
                for (int j = 0; j < 8; j++)
                    acc[i][j] += ar[i] * br[j];
        }
    }

    float* Cp = g_xproj + (size_t)(bm * 128 + ty * 8) * G4 + (size_t)(bn * 128 + tx * 8);
#pragma unroll
    for (int i = 0; i < 8; i++) {
        *(float4*)(Cp + (size_t)i * G4)     = make_float4(acc[i][0], acc[i][1], acc[i][2], acc[i][3]);
        *(float4*)(Cp + (size_t)i * G4 + 4) = make_float4(acc[i][4], acc[i][5], acc[i][6], acc[i][7]);
    }
}

// ============================================================================
// Kernel 2: persistent LSTM recurrence (R8 compute core, unchanged).
// 128 blocks x 256 threads (2 warps/SMSP). Block owns j in [bid*4, bid*4+4).
// Warp w: jl = w>>1, half = w&1. Thread = (batch b, j): all 4 gates.
// Per k4-iter: 1 strided h LDS.128 + 4 broadcast w LDS.128 + 8 FFMA2.
// NEW vs R8: two-level barrier arrival; cp.async h staging.
// ============================================================================
__global__ __launch_bounds__(TPB, 1)
void lstm_persist(const float* __restrict__ Whh,
                  const float* __restrict__ bih,
                  const float* __restrict__ bhh,
                  float* __restrict__ out)
{
    extern __shared__ float smem[];
    float* h_s = smem;                  // BB * HPAD
    float* w_s = smem + BB * HPAD;      // 16 * WPAD  (row r: gate r>>2, hidden r&3)

    const int tid  = threadIdx.x;
    const int bid  = blockIdx.x;
    const int lane = tid & 31;
    const int wid  = tid >> 5;          // 0..7
    const int jl   = wid >> 1;          // local hidden index 0..3
    const int half = wid & 1;           // batch half
    const int b    = half * 32 + lane;  // batch 0..63
    const int j    = bid * 4 + jl;      // global hidden index

    float* out_h = out;
    float* out_c = out + (size_t)SQ * BB * HD;

    // One-time: W_hh rows {g*512 + bid*4 + r} -> w_s[g*4+r][*], padded.
    for (int i = tid; i < 16 * (HD / 4); i += TPB) {
        int row = i >> 7, col = i & 127;
        int grow = (row >> 2) * HD + bid * 4 + (row & 3);
        *(float4*)(w_s + row * WPAD + (col << 2)) =
            *(const float4*)(Whh + (size_t)grow * HD + (col << 2));
    }
    // Biases for this thread's 4 gate columns.
    float bs0 = bih[0 * HD + j] + bhh[0 * HD + j];
    float bs1 = bih[1 * HD + j] + bhh[1 * HD + j];
    float bs2 = bih[2 * HD + j] + bhh[2 * HD + j];
    float bs3 = bih[3 * HD + j] + bhh[3 * HD + j];

    // h_0 = 0
    for (int i = tid; i < BB * HPAD; i += TPB) h_s[i] = 0.0f;
    __syncthreads();

    const ulonglong2* hr = (const ulonglong2*)(h_s + b * HPAD);
    const ulonglong2* w0 = (const ulonglong2*)(w_s + (0 * 4 + jl) * WPAD);
    const ulonglong2* w1 = (const ulonglong2*)(w_s + (1 * 4 + jl) * WPAD);
    const ulonglong2* w2 = (const ulonglong2*)(w_s + (2 * 4 + jl) * WPAD);
    const ulonglong2* w3 = (const ulonglong2*)(w_s + (3 * 4 + jl) * WPAD);

    float c = 0.0f;                     // register-resident cell state

    for (int t = 0; t < SQ; ++t) {
        // Prefetch x_proj (4 values): DRAM latency hides under the dot loop.
        const float* xq = g_xproj + ((size_t)t * BB + b) * G4 + j;
        float xp0 = __ldg(xq);
        float xp1 = __ldg(xq + 512);
        float xp2 = __ldg(xq + 1024);
        float xp3 = __ldg(xq + 1536);

        // 4 dot products (gates i,f,g,o), f32x2 packed along k.
        unsigned long long a0 = 0, a1 = 0, a2 = 0, a3 = 0;  // even-k pair acc
        unsigned long long e0 = 0, e1 = 0, e2 = 0, e3 = 0;  // odd-k pair acc
#pragma unroll 8
        for (int k = 0; k < HD / 4; ++k) {
            ulonglong2 hv = hr[k];
            ulonglong2 wv;
            wv = w0[k]; fma2(a0, hv.x, wv.x); fma2(e0, hv.y, wv.y);
            wv = w1[k]; fma2(a1, hv.x, wv.x); fma2(e1, hv.y, wv.y);
            wv = w2[k]; fma2(a2, hv.x, wv.x); fma2(e2, hv.y, wv.y);
            wv = w3[k]; fma2(a3, hv.x, wv.x); fma2(e3, hv.y, wv.y);
        }
        float v0 = red2(a0) + red2(e0);
        float v1 = red2(a1) + red2(e1);
        float v2 = red2(a2) + red2(e2);
        float v3 = red2(a3) + red2(e3);

        // Gates (torch order i, f, g, o) + local state update.
        float ig = sigf(v0 + xp0 + bs0);
        float fg = sigf(v1 + xp1 + bs1);
        float gg = tanhf(v2 + xp2 + bs2);
        float og = sigf(v3 + xp3 + bs3);
        c = fg * c + ig * gg;
        float h = og * tanhf(c);

        size_t o = (size_t)t * BB * HD + (size_t)b * HD + j;
        out_h[o] = h;
        out_c[o] = c;

        if (t + 1 < SQ) {
            gridbar2(bid);   // all h_t globally visible (two-level arrival)
            // Stage h_t into padded SMEM via cp.async: all 32 copies in flight
            // at once -> one L2 latency instead of ~8 serialized rounds.
            const float* hp = out_h + (size_t)t * BB * HD;
#pragma unroll
            for (int i = tid; i < BB * (HD / 4); i += TPB) {
                int bb2 = i >> 7, u = i & 127;
                cp16(h_s + bb2 * HPAD + (u << 2), hp + (i << 2));
            }
            cp_commit_wait();
            __syncthreads();
        }
    }
}

// ============================================================================
// Launch: inputs: x, W_ih, W_hh, b_ih, b_hh. Output: [h_out | c_out] fp32.
// ============================================================================
extern "C" void kernel_launch(void* const* d_in, const int* in_sizes, int n_in,
                              void* d_out, int out_size)
{
    (void)in_sizes; (void)n_in; (void)out_size;
    const float* x   = (const float*)d_in[0];
    const float* Wih = (const float*)d_in[1];
    const float* Whh = (const float*)d_in[2];
    const float* bih = (const float*)d_in[3];
    const float* bhh = (const float*)d_in[4];
    float* out = (float*)d_out;

    const int smem_bytes = (BB * HPAD + 16 * WPAD) * (int)sizeof(float);
    cudaFuncSetAttribute(lstm_persist, cudaFuncAttributeMaxDynamicSharedMemorySize, smem_bytes);

    dim3 g1(G4 / 128, (SQ * BB) / 128);   // (16, 1024)
    xproj_gemm<<<g1, 256>>>(x, Wih);
    lstm_persist<<<NBLK, TPB, smem_bytes>>>(Whh, bih, bhh, out);
}